// round 3
// baseline (speedup 1.0000x reference)
#include <cuda_runtime.h>

#define VSZ 32000
#define HSZ 256
#define BSZ 256
#define SSZ 512

typedef unsigned long long ull;

// Scratch (device globals; no allocation allowed)
__device__ float g_eproj[(size_t)VSZ * 768];   // emb @ [Wz;Wr;Wh]^T + biases
__device__ float g_hlast[BSZ * HSZ];
__device__ float g_uT[3 * 65536];              // transposed U: uT[g][k][j]

// ---- packed f32x2 helpers (Blackwell sm_103a) ----
__device__ __forceinline__ ull pk2(float lo, float hi) {
    ull r;
    asm("mov.b64 %0, {%1, %2};" : "=l"(r) : "f"(lo), "f"(hi));
    return r;
}
__device__ __forceinline__ void fma2(ull& d, ull a, ull b) {
    asm("fma.rn.f32x2 %0, %1, %2, %0;" : "+l"(d) : "l"(a), "l"(b));
}
__device__ __forceinline__ float fast_sigm(float x) {
    float e, r;
    asm("ex2.approx.ftz.f32 %0, %1;" : "=f"(e) : "f"(-1.4426950408889634f * x));
    asm("rcp.approx.ftz.f32 %0, %1;" : "=f"(r) : "f"(1.0f + e));
    return r;
}
__device__ __forceinline__ float fast_tanh(float x) {
    float r;
    asm("tanh.approx.f32 %0, %1;" : "=f"(r) : "f"(x));
    return r;
}

// ============================================================================
// U transpose: g_uT[g][k][j] = U_g[j][k]
// ============================================================================
__global__ void transpose_u(const float* __restrict__ Uz,
                            const float* __restrict__ Ur,
                            const float* __restrict__ Uh)
{
    __shared__ float tile[32][33];
    const int g = blockIdx.z;
    const float* U = (g == 0) ? Uz : (g == 1) ? Ur : Uh;
    const int x0 = blockIdx.x * 32, y0 = blockIdx.y * 32;
    tile[threadIdx.y][threadIdx.x] = U[(y0 + threadIdx.y) * 256 + x0 + threadIdx.x];
    __syncthreads();
    g_uT[g * 65536 + (x0 + threadIdx.y) * 256 + (y0 + threadIdx.x)] =
        tile[threadIdx.x][threadIdx.y];
}

// ============================================================================
// SGEMM-NT with bias (near f32x2 compute cap)
// ============================================================================
__global__ void __launch_bounds__(256) sgemm_nt_bias(
    const float* __restrict__ A, const float* __restrict__ Bw,
    const float* __restrict__ bias1, const float* __restrict__ bias2,
    float* __restrict__ C, int ldc, int coloff)
{
    __shared__ __align__(16) float As[16][132];
    __shared__ __align__(16) float Bs[16][132];
    const int t  = threadIdx.x;
    const int tm = t >> 4;
    const int tn = t & 15;

    ull acc[8][4];
#pragma unroll
    for (int i = 0; i < 8; i++)
#pragma unroll
        for (int j = 0; j < 4; j++) acc[i][j] = 0ULL;

    const float* Ab = A  + (size_t)blockIdx.x * 128 * 256;
    const float* Bb = Bw + (size_t)blockIdx.y * 128 * 256;
    const int lr = t >> 2;
    const int lk = (t & 3) << 2;

    for (int k0 = 0; k0 < 256; k0 += 16) {
        float4 a0 = *(const float4*)(Ab + (size_t)lr * 256 + k0 + lk);
        float4 a1 = *(const float4*)(Ab + (size_t)(lr + 64) * 256 + k0 + lk);
        float4 b0 = *(const float4*)(Bb + (size_t)lr * 256 + k0 + lk);
        float4 b1 = *(const float4*)(Bb + (size_t)(lr + 64) * 256 + k0 + lk);
        __syncthreads();
        As[lk + 0][lr] = a0.x; As[lk + 1][lr] = a0.y;
        As[lk + 2][lr] = a0.z; As[lk + 3][lr] = a0.w;
        As[lk + 0][lr + 64] = a1.x; As[lk + 1][lr + 64] = a1.y;
        As[lk + 2][lr + 64] = a1.z; As[lk + 3][lr + 64] = a1.w;
        Bs[lk + 0][lr] = b0.x; Bs[lk + 1][lr] = b0.y;
        Bs[lk + 2][lr] = b0.z; Bs[lk + 3][lr] = b0.w;
        Bs[lk + 0][lr + 64] = b1.x; Bs[lk + 1][lr + 64] = b1.y;
        Bs[lk + 2][lr + 64] = b1.z; Bs[lk + 3][lr + 64] = b1.w;
        __syncthreads();
#pragma unroll
        for (int kk = 0; kk < 16; kk++) {
            float4 av0 = *(const float4*)(&As[kk][tm * 8]);
            float4 av1 = *(const float4*)(&As[kk][tm * 8 + 4]);
            const ull* bp = (const ull*)(&Bs[kk][tn * 8]);
            ull b2_0 = bp[0], b2_1 = bp[1], b2_2 = bp[2], b2_3 = bp[3];
            float av[8] = {av0.x, av0.y, av0.z, av0.w, av1.x, av1.y, av1.z, av1.w};
#pragma unroll
            for (int i = 0; i < 8; i++) {
                ull a2 = pk2(av[i], av[i]);
                fma2(acc[i][0], a2, b2_0);
                fma2(acc[i][1], a2, b2_1);
                fma2(acc[i][2], a2, b2_2);
                fma2(acc[i][3], a2, b2_3);
            }
        }
    }

    const int row0 = blockIdx.x * 128 + tm * 8;
    const int col0 = blockIdx.y * 128 + tn * 8;
#pragma unroll
    for (int i = 0; i < 8; i++) {
#pragma unroll
        for (int j = 0; j < 4; j++) {
            float lo, hi;
            asm("mov.b64 {%0, %1}, %2;" : "=f"(lo), "=f"(hi) : "l"(acc[i][j]));
            int n0 = col0 + j * 2;
            float e0 = bias1[n0]     + (bias2 ? bias2[n0]     : 0.0f);
            float e1 = bias1[n0 + 1] + (bias2 ? bias2[n0 + 1] : 0.0f);
            C[(size_t)(row0 + i) * ldc + coloff + n0]     = lo + e0;
            C[(size_t)(row0 + i) * ldc + coloff + n0 + 1] = hi + e1;
        }
    }
}

// ============================================================================
// GRU scan v3: 64 CTAs x 4 batch rows x 512 threads.
// Compute split: kh = t>>7 (4 chunks of 64 k), jg = t&127 (2 cols each).
// Reduce split: thread t owns units u=2t,2t+1 -> (col = t>>1, m = 2(t&1)+{0,1}).
// Depth-4 rolling register prefetch of all three U streams with cross-step
// wraparound; tokens fetched 2 steps ahead, eproj values 1 step ahead.
// ============================================================================
#define SM_BYTES 180224   // pins 128KB + red 32KB + hdup 8KB + srhdup 8KB

__global__ void __launch_bounds__(512, 1) gru_scan3(const int* __restrict__ x)
{
    extern __shared__ float sm[];
    float* pin_z  = sm;                         // 16384 f: Uz_T k<64
    float* pin_r  = sm + 16384;                 // 16384 f: Ur_T k<64
    float* red    = sm + 32768;                 // 8192 f: [kh*4+m][col] (z), +4096 (r)
    ull*   hdup   = (ull*)(sm + 40960);         // 1024 ull: [k][m] pk2(h,h)
    ull*   srhdup = (ull*)(sm + 43008);         // 1024 ull: [k][m] pk2(r*h,r*h)

    const int t  = threadIdx.x;
    const int kh = t >> 7;            // 0..3
    const int jg = t & 127;           // 0..127
    const int c0 = jg * 2;
    const int kb = kh * 64;
    const int b0 = blockIdx.x * 4;

    // ---- init pinned U slices + zero state ----
    for (int i = t; i < 4096; i += 512) {
        ((float4*)pin_z)[i] = ((const float4*)g_uT)[i];
        ((float4*)pin_r)[i] = ((const float4*)(g_uT + 65536))[i];
    }
    for (int i = t; i < 1024; i += 512) { hdup[i] = 0ULL; srhdup[i] = 0ULL; }
    __syncthreads();

    // generic stream base pointers (smem for pinned chunks, global otherwise)
    const float* zsrc = (kh == 0) ? (pin_z + c0) : (g_uT + kb * 256 + c0);
    const float* rsrc = (kh == 0) ? (pin_r + c0) : (g_uT + 65536 + kb * 256 + c0);
    const float* hsrc = g_uT + 131072 + kb * 256 + c0;

    // ---- prime rolling buffers (persist across all steps) ----
    ull zb[4], rb[4], hb[4];
#pragma unroll
    for (int i = 0; i < 4; i++) {
        zb[i] = *(const ull*)(zsrc + i * 256);
        rb[i] = *(const ull*)(rsrc + i * 256);
        hb[i] = *(const ull*)(hsrc + i * 256);
    }

    // ---- reduce-unit identity + e/token pipeline ----
    const int col = t >> 1;
    const int m0  = (t & 1) * 2;
    const int rowA = b0 + m0, rowB = b0 + m0 + 1;
    float holdA = 0.0f, holdB = 0.0f;

    int tokA = __ldg(&x[rowA * SSZ]);
    int tokB = __ldg(&x[rowB * SSZ]);
    const float* eA = g_eproj + (size_t)tokA * 768;
    const float* eB = g_eproj + (size_t)tokB * 768;
    float ezA = __ldg(eA + col),       ezB = __ldg(eB + col);
    float erA = __ldg(eA + 256 + col), erB = __ldg(eB + 256 + col);
    float ehA = __ldg(eA + 512 + col), ehB = __ldg(eB + 512 + col);
    int tokA1 = __ldg(&x[rowA * SSZ + 1]);   // tokens for s+1
    int tokB1 = __ldg(&x[rowB * SSZ + 1]);

    for (int s = 0; s < SSZ; s++) {
        // ================= phase 1: z, r partials =================
        ull az[4] = {0, 0, 0, 0}, ar[4] = {0, 0, 0, 0};
#pragma unroll
        for (int kk = 0; kk < 64; kk++) {
            ull uz = zb[kk & 3];
            ull ur = rb[kk & 3];
            const int kp = (kk + 4) & 63;          // cross-step wraparound
            zb[kk & 3] = *(const ull*)(zsrc + kp * 256);
            rb[kk & 3] = *(const ull*)(rsrc + kp * 256);
            ulonglong2 hA = *(const ulonglong2*)(hdup + (kb + kk) * 4);
            ulonglong2 hB = *(const ulonglong2*)(hdup + (kb + kk) * 4 + 2);
            fma2(az[0], uz, hA.x); fma2(az[1], uz, hA.y);
            fma2(az[2], uz, hB.x); fma2(az[3], uz, hB.y);
            fma2(ar[0], ur, hA.x); fma2(ar[1], ur, hA.y);
            fma2(ar[2], ur, hB.x); fma2(ar[3], ur, hB.y);
        }
#pragma unroll
        for (int m = 0; m < 4; m++) {
            *(ull*)(red + (kh * 4 + m) * 256 + c0)        = az[m];
            *(ull*)(red + 4096 + (kh * 4 + m) * 256 + c0) = ar[m];
        }
        __syncthreads();

        // ================= reduce 1: z, r -> srh =================
        float szA = ezA, srA_ = erA, szB = ezB, srB_ = erB;
#pragma unroll
        for (int q = 0; q < 4; q++) {
            szA  += red[(q * 4 + m0) * 256 + col];
            srA_ += red[4096 + (q * 4 + m0) * 256 + col];
            szB  += red[(q * 4 + m0 + 1) * 256 + col];
            srB_ += red[4096 + (q * 4 + m0 + 1) * 256 + col];
        }
        const float zA = fast_sigm(szA), rA = fast_sigm(srA_);
        const float zB = fast_sigm(szB), rB = fast_sigm(srB_);
        {
            float a = rA * holdA, b = rB * holdB;
            *(ulonglong2*)(srhdup + col * 4 + m0) =
                make_ulonglong2(pk2(a, a), pk2(b, b));
        }
        // prefetch next step's z/r e-values (current ones consumed)
        {
            const float* enA = g_eproj + (size_t)tokA1 * 768;
            const float* enB = g_eproj + (size_t)tokB1 * 768;
            ezA = __ldg(enA + col);       ezB = __ldg(enB + col);
            erA = __ldg(enA + 256 + col); erB = __ldg(enB + 256 + col);
        }
        __syncthreads();

        // ================= phase 2: h_tilde partials =================
        ull ah[4] = {0, 0, 0, 0};
#pragma unroll
        for (int kk = 0; kk < 64; kk++) {
            ull uh = hb[kk & 3];
            const int kp = (kk + 4) & 63;
            hb[kk & 3] = *(const ull*)(hsrc + kp * 256);
            ulonglong2 sA = *(const ulonglong2*)(srhdup + (kb + kk) * 4);
            ulonglong2 sB = *(const ulonglong2*)(srhdup + (kb + kk) * 4 + 2);
            fma2(ah[0], uh, sA.x); fma2(ah[1], uh, sA.y);
            fma2(ah[2], uh, sB.x); fma2(ah[3], uh, sB.y);
        }
#pragma unroll
        for (int m = 0; m < 4; m++)
            *(ull*)(red + (kh * 4 + m) * 256 + c0) = ah[m];
        __syncthreads();

        // ================= reduce 2: h update =================
        float shA = ehA, shB = ehB;
#pragma unroll
        for (int q = 0; q < 4; q++) {
            shA += red[(q * 4 + m0) * 256 + col];
            shB += red[(q * 4 + m0 + 1) * 256 + col];
        }
        const float htA = fast_tanh(shA), htB = fast_tanh(shB);
        holdA += zA * (htA - holdA);
        holdB += zB * (htB - holdB);
        *(ulonglong2*)(hdup + col * 4 + m0) =
            make_ulonglong2(pk2(holdA, holdA), pk2(holdB, holdB));
        // prefetch next step's h e-values, then advance tokens to s+2
        {
            const float* enA = g_eproj + (size_t)tokA1 * 768;
            const float* enB = g_eproj + (size_t)tokB1 * 768;
            ehA = __ldg(enA + 512 + col);
            ehB = __ldg(enB + 512 + col);
            int s2 = (s + 2 < SSZ) ? s + 2 : SSZ - 1;
            tokA1 = __ldg(&x[rowA * SSZ + s2]);
            tokB1 = __ldg(&x[rowB * SSZ + s2]);
        }
        __syncthreads();
    }

    g_hlast[(size_t)rowA * HSZ + col] = holdA;
    g_hlast[(size_t)rowB * HSZ + col] = holdB;
}

// ============================================================================
extern "C" void kernel_launch(void* const* d_in, const int* in_sizes, int n_in,
                              void* d_out, int out_size)
{
    const int*   x   = (const int*)  d_in[0];
    const float* emb = (const float*)d_in[1];
    const float* Wz  = (const float*)d_in[2];
    const float* bz  = (const float*)d_in[3];
    const float* Uz  = (const float*)d_in[4];
    const float* buz = (const float*)d_in[5];
    const float* Wr  = (const float*)d_in[6];
    const float* br  = (const float*)d_in[7];
    const float* Ur  = (const float*)d_in[8];
    const float* bur = (const float*)d_in[9];
    const float* Wh  = (const float*)d_in[10];
    const float* bh  = (const float*)d_in[11];
    const float* Uh  = (const float*)d_in[12];
    const float* buh = (const float*)d_in[13];
    const float* Wf  = (const float*)d_in[14];
    const float* bf  = (const float*)d_in[15];
    float* out = (float*)d_out;

    float* eproj = nullptr;
    float* hlast = nullptr;
    cudaGetSymbolAddress((void**)&eproj, g_eproj);
    cudaGetSymbolAddress((void**)&hlast, g_hlast);

    cudaFuncSetAttribute(gru_scan3,
                         cudaFuncAttributeMaxDynamicSharedMemorySize, SM_BYTES);

    dim3 blk(256);
    transpose_u<<<dim3(8, 8, 3), dim3(32, 32)>>>(Uz, Ur, Uh);
    sgemm_nt_bias<<<dim3(250, 2), blk>>>(emb, Wz, bz, buz, eproj, 768, 0);
    sgemm_nt_bias<<<dim3(250, 2), blk>>>(emb, Wr, br, bur, eproj, 768, 256);
    sgemm_nt_bias<<<dim3(250, 2), blk>>>(emb, Wh, bh, buh, eproj, 768, 512);

    gru_scan3<<<64, 512, SM_BYTES>>>(x);

    sgemm_nt_bias<<<dim3(2, 250), blk>>>(hlast, Wf, bf, nullptr, out, 32000, 0);
}

// round 4
// speedup vs baseline: 1.6164x; 1.6164x over previous
#include <cuda_runtime.h>
#include <cuda_bf16.h>

#define VSZ 32000
#define HSZ 256
#define BSZ 256
#define SSZ 512

typedef unsigned long long ull;

// Scratch (device globals; no allocation allowed)
__device__ float g_eproj[(size_t)VSZ * 768];   // emb @ [Wz;Wr;Wh]^T + biases
__device__ float g_hlast[BSZ * HSZ];
// Packed bf16 U, transposed. uzr[k][jg] = {bf16x2(Uz[k-in][cols 2jg,2jg+1]), same Ur}
// uh2[k2][jg] = {bf16x2 Uh at k=2*k2, bf16x2 Uh at k=2*k2+1}
__device__ uint2 g_uzr[256 * 128];
__device__ uint2 g_uh2[128 * 128];

// ---- packed f32x2 helpers (Blackwell sm_103a) ----
__device__ __forceinline__ ull pk2(float lo, float hi) {
    ull r;
    asm("mov.b64 %0, {%1, %2};" : "=l"(r) : "f"(lo), "f"(hi));
    return r;
}
__device__ __forceinline__ void fma2(ull& d, ull a, ull b) {
    asm("fma.rn.f32x2 %0, %1, %2, %0;" : "+l"(d) : "l"(a), "l"(b));
}
// bf16x2 (lo in [15:0], hi in [31:16]) -> f32x2 pair, exact
__device__ __forceinline__ ull bf2f2(unsigned v) {
    ull r;
    asm("{\n\t.reg .b32 lo, hi;\n\t"
        "shl.b32 lo, %1, 16;\n\t"
        "and.b32 hi, %1, 0xFFFF0000;\n\t"
        "mov.b64 %0, {lo, hi};\n\t}" : "=l"(r) : "r"(v));
    return r;
}
__device__ __forceinline__ float fast_sigm(float x) {
    float e, r;
    asm("ex2.approx.ftz.f32 %0, %1;" : "=f"(e) : "f"(-1.4426950408889634f * x));
    asm("rcp.approx.ftz.f32 %0, %1;" : "=f"(r) : "f"(1.0f + e));
    return r;
}
__device__ __forceinline__ float fast_tanh(float x) {
    float r;
    asm("tanh.approx.f32 %0, %1;" : "=f"(r) : "f"(x));
    return r;
}
__device__ __forceinline__ unsigned pkbf(float lo, float hi) {
    unsigned short l = __bfloat16_as_ushort(__float2bfloat16(lo));
    unsigned short h = __bfloat16_as_ushort(__float2bfloat16(hi));
    return ((unsigned)h << 16) | (unsigned)l;
}

// ============================================================================
// Pack U into transposed bf16 streams
// ============================================================================
__global__ void pack_u(const float* __restrict__ Uz, const float* __restrict__ Ur,
                       const float* __restrict__ Uh)
{
    const int k  = blockIdx.x;     // 0..255 (input-k index)
    const int jg = threadIdx.x;    // 0..127 (output col pair)
    const int j0 = 2 * jg;
    unsigned z = pkbf(Uz[j0 * 256 + k], Uz[(j0 + 1) * 256 + k]);
    unsigned r = pkbf(Ur[j0 * 256 + k], Ur[(j0 + 1) * 256 + k]);
    g_uzr[k * 128 + jg] = make_uint2(z, r);
    if (k < 128) {
        const int k2 = k;
        unsigned h0 = pkbf(Uh[j0 * 256 + 2 * k2],     Uh[(j0 + 1) * 256 + 2 * k2]);
        unsigned h1 = pkbf(Uh[j0 * 256 + 2 * k2 + 1], Uh[(j0 + 1) * 256 + 2 * k2 + 1]);
        g_uh2[k2 * 128 + jg] = make_uint2(h0, h1);
    }
}

// ============================================================================
// SGEMM-NT with bias (unchanged; ~92% of scalar floor)
// ============================================================================
__global__ void __launch_bounds__(256) sgemm_nt_bias(
    const float* __restrict__ A, const float* __restrict__ Bw,
    const float* __restrict__ bias1, const float* __restrict__ bias2,
    float* __restrict__ C, int ldc, int coloff)
{
    __shared__ __align__(16) float As[16][132];
    __shared__ __align__(16) float Bs[16][132];
    const int t  = threadIdx.x;
    const int tm = t >> 4;
    const int tn = t & 15;

    ull acc[8][4];
#pragma unroll
    for (int i = 0; i < 8; i++)
#pragma unroll
        for (int j = 0; j < 4; j++) acc[i][j] = 0ULL;

    const float* Ab = A  + (size_t)blockIdx.x * 128 * 256;
    const float* Bb = Bw + (size_t)blockIdx.y * 128 * 256;
    const int lr = t >> 2;
    const int lk = (t & 3) << 2;

    for (int k0 = 0; k0 < 256; k0 += 16) {
        float4 a0 = *(const float4*)(Ab + (size_t)lr * 256 + k0 + lk);
        float4 a1 = *(const float4*)(Ab + (size_t)(lr + 64) * 256 + k0 + lk);
        float4 b0 = *(const float4*)(Bb + (size_t)lr * 256 + k0 + lk);
        float4 b1 = *(const float4*)(Bb + (size_t)(lr + 64) * 256 + k0 + lk);
        __syncthreads();
        As[lk + 0][lr] = a0.x; As[lk + 1][lr] = a0.y;
        As[lk + 2][lr] = a0.z; As[lk + 3][lr] = a0.w;
        As[lk + 0][lr + 64] = a1.x; As[lk + 1][lr + 64] = a1.y;
        As[lk + 2][lr + 64] = a1.z; As[lk + 3][lr + 64] = a1.w;
        Bs[lk + 0][lr] = b0.x; Bs[lk + 1][lr] = b0.y;
        Bs[lk + 2][lr] = b0.z; Bs[lk + 3][lr] = b0.w;
        Bs[lk + 0][lr + 64] = b1.x; Bs[lk + 1][lr + 64] = b1.y;
        Bs[lk + 2][lr + 64] = b1.z; Bs[lk + 3][lr + 64] = b1.w;
        __syncthreads();
#pragma unroll
        for (int kk = 0; kk < 16; kk++) {
            float4 av0 = *(const float4*)(&As[kk][tm * 8]);
            float4 av1 = *(const float4*)(&As[kk][tm * 8 + 4]);
            const ull* bp = (const ull*)(&Bs[kk][tn * 8]);
            ull b2_0 = bp[0], b2_1 = bp[1], b2_2 = bp[2], b2_3 = bp[3];
            float av[8] = {av0.x, av0.y, av0.z, av0.w, av1.x, av1.y, av1.z, av1.w};
#pragma unroll
            for (int i = 0; i < 8; i++) {
                ull a2 = pk2(av[i], av[i]);
                fma2(acc[i][0], a2, b2_0);
                fma2(acc[i][1], a2, b2_1);
                fma2(acc[i][2], a2, b2_2);
                fma2(acc[i][3], a2, b2_3);
            }
        }
    }

    const int row0 = blockIdx.x * 128 + tm * 8;
    const int col0 = blockIdx.y * 128 + tn * 8;
#pragma unroll
    for (int i = 0; i < 8; i++) {
#pragma unroll
        for (int j = 0; j < 4; j++) {
            float lo, hi;
            asm("mov.b64 {%0, %1}, %2;" : "=f"(lo), "=f"(hi) : "l"(acc[i][j]));
            int n0 = col0 + j * 2;
            float e0 = bias1[n0]     + (bias2 ? bias2[n0]     : 0.0f);
            float e1 = bias1[n0 + 1] + (bias2 ? bias2[n0 + 1] : 0.0f);
            C[(size_t)(row0 + i) * ldc + coloff + n0]     = lo + e0;
            C[(size_t)(row0 + i) * ldc + coloff + n0 + 1] = hi + e1;
        }
    }
}

// ============================================================================
// GRU scan v4: 128 CTAs x 2 batch rows x 512 threads, bf16 U streams.
// Compute split: kh = t>>7 (4 chunks of 64 k), jg = t&127 (col pair 2jg,2jg+1).
// Reduce split: thread t -> (col = t>>1, m = t&1), one (row,col) unit.
// SMEM pins U for k<64 (96KB bf16) -> also forces 1 CTA/SM.
// ============================================================================
#define SM_BYTES 122880

__global__ void __launch_bounds__(512, 1) gru_scan4(const int* __restrict__ x)
{
    extern __shared__ __align__(16) char smraw[];
    uint2* pin_zr = (uint2*)smraw;                    // 8192 uint2 (64KB), k<64
    uint2* pin_h2 = (uint2*)(smraw + 65536);          // 4096 uint2 (32KB), k2<32
    float* red    = (float*)(smraw + 98304);          // 4096 f (16KB)
    ull*   hdup   = (ull*)(smraw + 114688);           // 512 ull: [k][m]
    ull*   srhdup = (ull*)(smraw + 118784);           // 512 ull: [k][m]

    const int t  = threadIdx.x;
    const int kh = t >> 7;            // 0..3
    const int jg = t & 127;           // 0..127
    const int c0 = jg * 2;
    const int kb = kh * 64;
    const int b0 = blockIdx.x * 2;

    // ---- pin U k<64 + zero state ----
    for (int i = t; i < 8192; i += 512) pin_zr[i] = g_uzr[i];
    for (int i = t; i < 4096; i += 512) pin_h2[i] = g_uh2[i];
    for (int i = t; i < 512; i += 512) { }   // (no-op; state below)
    if (t < 512) { hdup[t] = 0ULL; srhdup[t] = 0ULL; }
    __syncthreads();

    // stream base pointers (smem for kh==0, global otherwise; generic LD)
    const uint2* zrsrc = (kh == 0) ? (pin_zr + jg) : (g_uzr + kb * 128 + jg);
    const uint2* h2src = (kh == 0) ? (pin_h2 + jg) : (g_uh2 + (kh * 32) * 128 + jg);

    // ---- prime rolling buffers (persist across all steps) ----
    uint2 zrb[4], hb2[4];
#pragma unroll
    for (int i = 0; i < 4; i++) {
        zrb[i] = zrsrc[i * 128];
        hb2[i] = h2src[i * 128];
    }

    // ---- reduce-unit identity + e/token pipeline ----
    const int col = t >> 1;
    const int m   = t & 1;
    const int row = b0 + m;
    float hold = 0.0f;

    int tok0 = __ldg(&x[row * SSZ]);
    const float* e0p = g_eproj + (size_t)tok0 * 768;
    float ez = __ldg(e0p + col);
    float er = __ldg(e0p + 256 + col);
    float eh = __ldg(e0p + 512 + col);
    int tok1 = __ldg(&x[row * SSZ + 1]);

    float zgate = 0.0f;

    for (int s = 0; s < SSZ; s++) {
        // ================= phase 1: z, r partials =================
        ull az[2] = {0, 0}, ar[2] = {0, 0};
#pragma unroll
        for (int kk = 0; kk < 64; kk++) {
            uint2 u = zrb[kk & 3];
            zrb[kk & 3] = zrsrc[((kk + 4) & 63) * 128];   // cross-step wrap
            ull uz = bf2f2(u.x);
            ull ur = bf2f2(u.y);
            ulonglong2 hp = *(const ulonglong2*)(hdup + (kb + kk) * 2);
            fma2(az[0], uz, hp.x); fma2(az[1], uz, hp.y);
            fma2(ar[0], ur, hp.x); fma2(ar[1], ur, hp.y);
        }
#pragma unroll
        for (int mm = 0; mm < 2; mm++) {
            *(ull*)(red + (kh * 4 + mm) * 256 + c0)     = az[mm];
            *(ull*)(red + (kh * 4 + 2 + mm) * 256 + c0) = ar[mm];
        }
        __syncthreads();

        // ================= reduce 1: z, r -> srh =================
        float sz = ez, sr = er;
#pragma unroll
        for (int q = 0; q < 4; q++) {
            sz += red[(q * 4 + m) * 256 + col];
            sr += red[(q * 4 + 2 + m) * 256 + col];
        }
        zgate = fast_sigm(sz);
        float rg = fast_sigm(sr);
        float rh = rg * hold;
        srhdup[col * 2 + m] = pk2(rh, rh);
        // prefetch next step's z/r e-values
        {
            const float* en = g_eproj + (size_t)tok1 * 768;
            ez = __ldg(en + col);
            er = __ldg(en + 256 + col);
        }
        __syncthreads();

        // ================= phase 2: h_tilde partials =================
        ull ah[2] = {0, 0};
#pragma unroll
        for (int kk = 0; kk < 32; kk++) {
            uint2 u = hb2[kk & 3];
            hb2[kk & 3] = h2src[((kk + 4) & 31) * 128];
            ull uh0 = bf2f2(u.x);
            ull uh1 = bf2f2(u.y);
            const int k0 = kb + 2 * kk;
            ulonglong2 s0 = *(const ulonglong2*)(srhdup + k0 * 2);
            ulonglong2 s1 = *(const ulonglong2*)(srhdup + k0 * 2 + 2);
            fma2(ah[0], uh0, s0.x); fma2(ah[1], uh0, s0.y);
            fma2(ah[0], uh1, s1.x); fma2(ah[1], uh1, s1.y);
        }
#pragma unroll
        for (int mm = 0; mm < 2; mm++)
            *(ull*)(red + (kh * 4 + mm) * 256 + c0) = ah[mm];
        __syncthreads();

        // ================= reduce 2: h update =================
        float sh = eh;
#pragma unroll
        for (int q = 0; q < 4; q++)
            sh += red[(q * 4 + m) * 256 + col];
        float ht = fast_tanh(sh);
        hold += zgate * (ht - hold);
        hdup[col * 2 + m] = pk2(hold, hold);
        // prefetch next step's h e-value; advance token pipeline
        {
            const float* en = g_eproj + (size_t)tok1 * 768;
            eh = __ldg(en + 512 + col);
            int s2 = (s + 2 < SSZ) ? s + 2 : SSZ - 1;
            tok1 = __ldg(&x[row * SSZ + s2]);
        }
        __syncthreads();
    }

    g_hlast[(size_t)row * HSZ + col] = hold;
}

// ============================================================================
extern "C" void kernel_launch(void* const* d_in, const int* in_sizes, int n_in,
                              void* d_out, int out_size)
{
    const int*   x   = (const int*)  d_in[0];
    const float* emb = (const float*)d_in[1];
    const float* Wz  = (const float*)d_in[2];
    const float* bz  = (const float*)d_in[3];
    const float* Uz  = (const float*)d_in[4];
    const float* buz = (const float*)d_in[5];
    const float* Wr  = (const float*)d_in[6];
    const float* br  = (const float*)d_in[7];
    const float* Ur  = (const float*)d_in[8];
    const float* bur = (const float*)d_in[9];
    const float* Wh  = (const float*)d_in[10];
    const float* bh  = (const float*)d_in[11];
    const float* Uh  = (const float*)d_in[12];
    const float* buh = (const float*)d_in[13];
    const float* Wf  = (const float*)d_in[14];
    const float* bf  = (const float*)d_in[15];
    float* out = (float*)d_out;

    float* eproj = nullptr;
    float* hlast = nullptr;
    cudaGetSymbolAddress((void**)&eproj, g_eproj);
    cudaGetSymbolAddress((void**)&hlast, g_hlast);

    cudaFuncSetAttribute(gru_scan4,
                         cudaFuncAttributeMaxDynamicSharedMemorySize, SM_BYTES);

    dim3 blk(256);
    pack_u<<<256, 128>>>(Uz, Ur, Uh);
    sgemm_nt_bias<<<dim3(250, 2), blk>>>(emb, Wz, bz, buz, eproj, 768, 0);
    sgemm_nt_bias<<<dim3(250, 2), blk>>>(emb, Wr, br, bur, eproj, 768, 256);
    sgemm_nt_bias<<<dim3(250, 2), blk>>>(emb, Wh, bh, buh, eproj, 768, 512);

    gru_scan4<<<128, 512, SM_BYTES>>>(x);

    sgemm_nt_bias<<<dim3(2, 250), blk>>>(hlast, Wf, bf, nullptr, out, 32000, 0);
}

// round 5
// speedup vs baseline: 1.6639x; 1.0294x over previous
#include <cuda_runtime.h>
#include <cuda_bf16.h>

#define VSZ 32000
#define HSZ 256
#define BSZ 256
#define SSZ 512

typedef unsigned long long ull;

// Scratch (device globals; no allocation allowed)
__device__ float g_eproj[(size_t)VSZ * 768];   // emb @ [Wz;Wr;Wh]^T + biases
__device__ float g_hlast[BSZ * HSZ];
// Packed bf16 U, transposed. uzr[k][jg] = {bf16x2(Uz cols 2jg,2jg+1), same Ur}
// uh2[k2][jg] = {bf16x2 Uh at k=2*k2, bf16x2 Uh at k=2*k2+1}
__device__ uint2 g_uzr[256 * 128];
__device__ uint2 g_uh2[128 * 128];

// ---- packed f32x2 helpers (Blackwell sm_103a) ----
__device__ __forceinline__ ull pk2(float lo, float hi) {
    ull r;
    asm("mov.b64 %0, {%1, %2};" : "=l"(r) : "f"(lo), "f"(hi));
    return r;
}
__device__ __forceinline__ void fma2(ull& d, ull a, ull b) {
    asm("fma.rn.f32x2 %0, %1, %2, %0;" : "+l"(d) : "l"(a), "l"(b));
}
// bf16x2 (lo in [15:0], hi in [31:16]) -> f32x2 pair, exact
__device__ __forceinline__ ull bf2f2(unsigned v) {
    ull r;
    asm("{\n\t.reg .b32 lo, hi;\n\t"
        "shl.b32 lo, %1, 16;\n\t"
        "and.b32 hi, %1, 0xFFFF0000;\n\t"
        "mov.b64 %0, {lo, hi};\n\t}" : "=l"(r) : "r"(v));
    return r;
}
__device__ __forceinline__ float fast_sigm(float x) {
    float e, r;
    asm("ex2.approx.ftz.f32 %0, %1;" : "=f"(e) : "f"(-1.4426950408889634f * x));
    asm("rcp.approx.ftz.f32 %0, %1;" : "=f"(r) : "f"(1.0f + e));
    return r;
}
__device__ __forceinline__ float fast_tanh(float x) {
    float r;
    asm("tanh.approx.f32 %0, %1;" : "=f"(r) : "f"(x));
    return r;
}
__device__ __forceinline__ unsigned pkbf(float lo, float hi) {
    unsigned short l = __bfloat16_as_ushort(__float2bfloat16(lo));
    unsigned short h = __bfloat16_as_ushort(__float2bfloat16(hi));
    return ((unsigned)h << 16) | (unsigned)l;
}

// ============================================================================
// Pack U into transposed bf16 streams
// ============================================================================
__global__ void pack_u(const float* __restrict__ Uz, const float* __restrict__ Ur,
                       const float* __restrict__ Uh)
{
    const int k  = blockIdx.x;     // 0..255 (input-k index)
    const int jg = threadIdx.x;    // 0..127 (output col pair)
    const int j0 = 2 * jg;
    unsigned z = pkbf(Uz[j0 * 256 + k], Uz[(j0 + 1) * 256 + k]);
    unsigned r = pkbf(Ur[j0 * 256 + k], Ur[(j0 + 1) * 256 + k]);
    g_uzr[k * 128 + jg] = make_uint2(z, r);
    if (k < 128) {
        const int k2 = k;
        unsigned h0 = pkbf(Uh[j0 * 256 + 2 * k2],     Uh[(j0 + 1) * 256 + 2 * k2]);
        unsigned h1 = pkbf(Uh[j0 * 256 + 2 * k2 + 1], Uh[(j0 + 1) * 256 + 2 * k2 + 1]);
        g_uh2[k2 * 128 + jg] = make_uint2(h0, h1);
    }
}

// ============================================================================
// SGEMM-NT with bias (~70-90% of scalar f32x2 floor)
// ============================================================================
__global__ void __launch_bounds__(256) sgemm_nt_bias(
    const float* __restrict__ A, const float* __restrict__ Bw,
    const float* __restrict__ bias1, const float* __restrict__ bias2,
    float* __restrict__ C, int ldc, int coloff)
{
    __shared__ __align__(16) float As[16][132];
    __shared__ __align__(16) float Bs[16][132];
    const int t  = threadIdx.x;
    const int tm = t >> 4;
    const int tn = t & 15;

    ull acc[8][4];
#pragma unroll
    for (int i = 0; i < 8; i++)
#pragma unroll
        for (int j = 0; j < 4; j++) acc[i][j] = 0ULL;

    const float* Ab = A  + (size_t)blockIdx.x * 128 * 256;
    const float* Bb = Bw + (size_t)blockIdx.y * 128 * 256;
    const int lr = t >> 2;
    const int lk = (t & 3) << 2;

    for (int k0 = 0; k0 < 256; k0 += 16) {
        float4 a0 = *(const float4*)(Ab + (size_t)lr * 256 + k0 + lk);
        float4 a1 = *(const float4*)(Ab + (size_t)(lr + 64) * 256 + k0 + lk);
        float4 b0 = *(const float4*)(Bb + (size_t)lr * 256 + k0 + lk);
        float4 b1 = *(const float4*)(Bb + (size_t)(lr + 64) * 256 + k0 + lk);
        __syncthreads();
        As[lk + 0][lr] = a0.x; As[lk + 1][lr] = a0.y;
        As[lk + 2][lr] = a0.z; As[lk + 3][lr] = a0.w;
        As[lk + 0][lr + 64] = a1.x; As[lk + 1][lr + 64] = a1.y;
        As[lk + 2][lr + 64] = a1.z; As[lk + 3][lr + 64] = a1.w;
        Bs[lk + 0][lr] = b0.x; Bs[lk + 1][lr] = b0.y;
        Bs[lk + 2][lr] = b0.z; Bs[lk + 3][lr] = b0.w;
        Bs[lk + 0][lr + 64] = b1.x; Bs[lk + 1][lr + 64] = b1.y;
        Bs[lk + 2][lr + 64] = b1.z; Bs[lk + 3][lr + 64] = b1.w;
        __syncthreads();
#pragma unroll
        for (int kk = 0; kk < 16; kk++) {
            float4 av0 = *(const float4*)(&As[kk][tm * 8]);
            float4 av1 = *(const float4*)(&As[kk][tm * 8 + 4]);
            const ull* bp = (const ull*)(&Bs[kk][tn * 8]);
            ull b2_0 = bp[0], b2_1 = bp[1], b2_2 = bp[2], b2_3 = bp[3];
            float av[8] = {av0.x, av0.y, av0.z, av0.w, av1.x, av1.y, av1.z, av1.w};
#pragma unroll
            for (int i = 0; i < 8; i++) {
                ull a2 = pk2(av[i], av[i]);
                fma2(acc[i][0], a2, b2_0);
                fma2(acc[i][1], a2, b2_1);
                fma2(acc[i][2], a2, b2_2);
                fma2(acc[i][3], a2, b2_3);
            }
        }
    }

    const int row0 = blockIdx.x * 128 + tm * 8;
    const int col0 = blockIdx.y * 128 + tn * 8;
#pragma unroll
    for (int i = 0; i < 8; i++) {
#pragma unroll
        for (int j = 0; j < 4; j++) {
            float lo, hi;
            asm("mov.b64 {%0, %1}, %2;" : "=f"(lo), "=f"(hi) : "l"(acc[i][j]));
            int n0 = col0 + j * 2;
            float e0 = bias1[n0]     + (bias2 ? bias2[n0]     : 0.0f);
            float e1 = bias1[n0 + 1] + (bias2 ? bias2[n0 + 1] : 0.0f);
            C[(size_t)(row0 + i) * ldc + coloff + n0]     = lo + e0;
            C[(size_t)(row0 + i) * ldc + coloff + n0 + 1] = hi + e1;
        }
    }
}

// ============================================================================
// GRU scan v5: 128 CTAs x 2 batch rows x 512 threads, bf16 U streams.
// Round-5 deltas: pin k<128 of ALL THREE U streams in SMEM (192KB; halves L2
// traffic below the fma2 rt-floor) and deepen the rolling register prefetch
// to 8 so the remaining global streams (kh=2,3) cover L2 latency.
// ============================================================================
#define SM_BYTES 221184   // 128K pin_zr + 64K pin_h2 + 16K red + 8K state

__global__ void __launch_bounds__(512, 1) gru_scan5(const int* __restrict__ x)
{
    extern __shared__ __align__(16) char smraw[];
    uint2* pin_zr = (uint2*)smraw;                    // 16384 uint2: k<128
    uint2* pin_h2 = (uint2*)(smraw + 131072);         // 8192 uint2: k2<64
    float* red    = (float*)(smraw + 196608);         // 4096 f (16KB)
    ull*   hdup   = (ull*)(smraw + 212992);           // 512 ull: [col][m]
    ull*   srhdup = (ull*)(smraw + 217088);           // 512 ull: [col][m]

    const int t  = threadIdx.x;
    const int kh = t >> 7;            // 0..3
    const int jg = t & 127;           // 0..127
    const int c0 = jg * 2;
    const int kb = kh * 64;
    const int b0 = blockIdx.x * 2;

    // ---- pin U k<128 + zero state ----
    for (int i = t; i < 16384; i += 512) pin_zr[i] = g_uzr[i];
    for (int i = t; i < 8192; i += 512)  pin_h2[i] = g_uh2[i];
    if (t < 512) { hdup[t] = 0ULL; srhdup[t] = 0ULL; }
    __syncthreads();

    // stream base pointers (smem for kh<2, global otherwise; generic LD)
    const uint2* zrsrc = (kh < 2) ? (pin_zr + kb * 128 + jg)
                                  : (g_uzr + kb * 128 + jg);
    const uint2* h2src = (kh < 2) ? (pin_h2 + (kh * 32) * 128 + jg)
                                  : (g_uh2 + (kh * 32) * 128 + jg);

    // ---- prime depth-8 rolling buffers (persist across all steps) ----
    uint2 zrb[8], hb2[8];
#pragma unroll
    for (int i = 0; i < 8; i++) {
        zrb[i] = zrsrc[i * 128];
        hb2[i] = h2src[(i & 7) * 128 % (32 * 128)];
    }
#pragma unroll
    for (int i = 0; i < 8; i++) hb2[i] = h2src[(i % 32) * 128];

    // ---- reduce-unit identity + e/token pipeline ----
    const int col = t >> 1;
    const int m   = t & 1;
    const int row = b0 + m;
    float hold = 0.0f;

    int tok0 = __ldg(&x[row * SSZ]);
    const float* e0p = g_eproj + (size_t)tok0 * 768;
    float ez = __ldg(e0p + col);
    float er = __ldg(e0p + 256 + col);
    float eh = __ldg(e0p + 512 + col);
    int tok1 = __ldg(&x[row * SSZ + 1]);

    float zgate = 0.0f;

    for (int s = 0; s < SSZ; s++) {
        // ================= phase 1: z, r partials =================
        ull az[2] = {0, 0}, ar[2] = {0, 0};
#pragma unroll
        for (int kk = 0; kk < 64; kk++) {
            uint2 u = zrb[kk & 7];
            zrb[kk & 7] = zrsrc[((kk + 8) & 63) * 128];   // cross-step wrap
            ull uz = bf2f2(u.x);
            ull ur = bf2f2(u.y);
            ulonglong2 hp = *(const ulonglong2*)(hdup + (kb + kk) * 2);
            fma2(az[0], uz, hp.x); fma2(az[1], uz, hp.y);
            fma2(ar[0], ur, hp.x); fma2(ar[1], ur, hp.y);
        }
#pragma unroll
        for (int mm = 0; mm < 2; mm++) {
            *(ull*)(red + (kh * 4 + mm) * 256 + c0)     = az[mm];
            *(ull*)(red + (kh * 4 + 2 + mm) * 256 + c0) = ar[mm];
        }
        __syncthreads();

        // ================= reduce 1: z, r -> srh =================
        float sz = ez, sr = er;
#pragma unroll
        for (int q = 0; q < 4; q++) {
            sz += red[(q * 4 + m) * 256 + col];
            sr += red[(q * 4 + 2 + m) * 256 + col];
        }
        zgate = fast_sigm(sz);
        float rg = fast_sigm(sr);
        float rh = rg * hold;
        srhdup[col * 2 + m] = pk2(rh, rh);
        // prefetch next step's z/r e-values
        {
            const float* en = g_eproj + (size_t)tok1 * 768;
            ez = __ldg(en + col);
            er = __ldg(en + 256 + col);
        }
        __syncthreads();

        // ================= phase 2: h_tilde partials =================
        ull ah[2] = {0, 0};
#pragma unroll
        for (int kk = 0; kk < 32; kk++) {
            uint2 u = hb2[kk & 7];
            hb2[kk & 7] = h2src[((kk + 8) & 31) * 128];
            ull uh0 = bf2f2(u.x);
            ull uh1 = bf2f2(u.y);
            const int k0 = kb + 2 * kk;
            ulonglong2 s0 = *(const ulonglong2*)(srhdup + k0 * 2);
            ulonglong2 s1 = *(const ulonglong2*)(srhdup + k0 * 2 + 2);
            fma2(ah[0], uh0, s0.x); fma2(ah[1], uh0, s0.y);
            fma2(ah[0], uh1, s1.x); fma2(ah[1], uh1, s1.y);
        }
#pragma unroll
        for (int mm = 0; mm < 2; mm++)
            *(ull*)(red + (kh * 4 + mm) * 256 + c0) = ah[mm];
        __syncthreads();

        // ================= reduce 2: h update =================
        float sh = eh;
#pragma unroll
        for (int q = 0; q < 4; q++)
            sh += red[(q * 4 + m) * 256 + col];
        float ht = fast_tanh(sh);
        hold += zgate * (ht - hold);
        hdup[col * 2 + m] = pk2(hold, hold);
        // prefetch next step's h e-value; advance token pipeline
        {
            const float* en = g_eproj + (size_t)tok1 * 768;
            eh = __ldg(en + 512 + col);
            int s2 = (s + 2 < SSZ) ? s + 2 : SSZ - 1;
            tok1 = __ldg(&x[row * SSZ + s2]);
        }
        __syncthreads();
    }

    g_hlast[(size_t)row * HSZ + col] = hold;
}

// ============================================================================
extern "C" void kernel_launch(void* const* d_in, const int* in_sizes, int n_in,
                              void* d_out, int out_size)
{
    const int*   x   = (const int*)  d_in[0];
    const float* emb = (const float*)d_in[1];
    const float* Wz  = (const float*)d_in[2];
    const float* bz  = (const float*)d_in[3];
    const float* Uz  = (const float*)d_in[4];
    const float* buz = (const float*)d_in[5];
    const float* Wr  = (const float*)d_in[6];
    const float* br  = (const float*)d_in[7];
    const float* Ur  = (const float*)d_in[8];
    const float* bur = (const float*)d_in[9];
    const float* Wh  = (const float*)d_in[10];
    const float* bh  = (const float*)d_in[11];
    const float* Uh  = (const float*)d_in[12];
    const float* buh = (const float*)d_in[13];
    const float* Wf  = (const float*)d_in[14];
    const float* bf  = (const float*)d_in[15];
    float* out = (float*)d_out;

    float* eproj = nullptr;
    float* hlast = nullptr;
    cudaGetSymbolAddress((void**)&eproj, g_eproj);
    cudaGetSymbolAddress((void**)&hlast, g_hlast);

    cudaFuncSetAttribute(gru_scan5,
                         cudaFuncAttributeMaxDynamicSharedMemorySize, SM_BYTES);

    dim3 blk(256);
    pack_u<<<256, 128>>>(Uz, Ur, Uh);
    sgemm_nt_bias<<<dim3(250, 2), blk>>>(emb, Wz, bz, buz, eproj, 768, 0);
    sgemm_nt_bias<<<dim3(250, 2), blk>>>(emb, Wr, br, bur, eproj, 768, 256);
    sgemm_nt_bias<<<dim3(250, 2), blk>>>(emb, Wh, bh, buh, eproj, 768, 512);

    gru_scan5<<<128, 512, SM_BYTES>>>(x);

    sgemm_nt_bias<<<dim3(2, 250), blk>>>(hlast, Wf, bf, nullptr, out, 32000, 0);
}